// round 11
// baseline (speedup 1.0000x reference)
#include <cuda_runtime.h>
#include <cuda_fp16.h>
#include <cstdint>
#include <math.h>

#define TPB 256

static __device__ __forceinline__ uint32_t s2u(const void* p) {
    uint32_t a;
    asm("{ .reg .u64 t; cvta.to.shared.u64 t, %1; cvt.u32.u64 %0, t; }" : "=r"(a) : "l"(p));
    return a;
}
static __device__ __forceinline__ float fast_exp2(float x) {
    float y; asm("ex2.approx.ftz.f32 %0, %1;" : "=f"(y) : "f"(x)); return y;
}
static __device__ __forceinline__ uint32_t pack_h2(float lo, float hi) {
    uint32_t u;
    asm("cvt.rn.f16x2.f32 %0, %1, %2;" : "=r"(u) : "f"(hi), "f"(lo));  // d.lo = %2
    return u;
}
static __device__ __forceinline__ uint32_t hmul2(uint32_t a, uint32_t b) {
    uint32_t d;
    asm("mul.rn.f16x2 %0, %1, %2;" : "=r"(d) : "r"(a), "r"(b));
    return d;
}
static __device__ __forceinline__ uint32_t sw128(uint32_t off) {
    return off ^ ((off >> 3) & 0x70);
}
static __device__ __forceinline__ void ldsm_x4(uint32_t addr, uint32_t& r0, uint32_t& r1,
                                               uint32_t& r2, uint32_t& r3) {
    asm volatile("ldmatrix.sync.aligned.m8n8.x4.shared.b16 {%0,%1,%2,%3}, [%4];"
                 : "=r"(r0), "=r"(r1), "=r"(r2), "=r"(r3) : "r"(addr));
}
static __device__ __forceinline__ void mma16816(float* c, uint32_t a0, uint32_t a1,
                                                uint32_t a2, uint32_t a3,
                                                uint32_t b0, uint32_t b1) {
    asm volatile(
        "mma.sync.aligned.m16n8k16.row.col.f32.f16.f16.f32 "
        "{%0,%1,%2,%3}, {%4,%5,%6,%7}, {%8,%9}, {%0,%1,%2,%3};"
        : "+f"(c[0]), "+f"(c[1]), "+f"(c[2]), "+f"(c[3])
        : "r"(a0), "r"(a1), "r"(a2), "r"(a3), "r"(b0), "r"(b1));
}
static __device__ __forceinline__ void red_v2(float* p, float x, float y) {
    asm volatile("red.global.add.v2.f32 [%0], {%1, %2};"
                 :: "l"(p), "f"(x), "f"(y) : "memory");
}

// dynamic smem: B[384x64p fp16, SW128 rows] | A[16x64p] | bx,by[256] | vch2[3][128] | vsm[768]
#define OFF_B    0          // 49152 B
#define OFF_A    49152      // 2048 B
#define OFF_BX   51200      // 1024 B
#define OFF_BY   52224      // 1024 B
#define OFF_VH   53248      // 1536 B (u32 f16x2 point-pairs per channel)
#define OFF_VS   54784      // 3072 B (raw values, init only)
#define SMEM_SZ  57856

// CTA = (kp chunk of 256 points, h-quarter of 16 rows, batch n).  128 CTAs = one wave.
// out[16h x (3c x 128w)] += sum_p ey[h,p] * (ex[w,p] * v[p,c])  via red.global.v2
__global__ void __launch_bounds__(TPB)
splat2d_hmma_kernel(const float* __restrict__ coords,   // [N,P,2]
                    const float* __restrict__ values,   // [N,P,3]
                    const float* __restrict__ sigma,    // [N,1]
                    float* __restrict__ out,            // [N,3,128,128]
                    int P) {
    extern __shared__ __align__(1024) char smem[];
    float*    bx   = (float*)(smem + OFF_BX);
    float*    by   = (float*)(smem + OFF_BY);
    uint32_t* vch2 = (uint32_t*)(smem + OFF_VH);   // [c][pair] = (v[2q],v[2q+1]) f16x2
    float*    vsm  = (float*)(smem + OFF_VS);

    const int tid = threadIdx.x;
    const int kp  = blockIdx.x >> 3;        // 0..3  (256-point chunk)
    const int hq  = blockIdx.x & 7;         // 0..7  (16-row tile)
    const int n   = blockIdx.y;
    const int p0  = kp * 256;
    const int hbase = hq * 16;

    const float sg = sigma[n];
    const float a_ = sqrtf(0.72134752044448169f) / sg;   // sqrt(log2(e)/2)/sigma

    const float2* cb2 = (const float2*)coords + (size_t)n * P;
    const float*  vb  = values + (size_t)n * P * 3;

    // ---- stage chunk tables ----
    {
        const float2 cd = cb2[p0 + tid];
        bx[tid] = a_ * cd.x;
        by[tid] = a_ * cd.y;
    }
    for (int i = tid; i < 768; i += TPB) vsm[i] = vb[p0 * 3 + i];
    __syncthreads();
    if (tid < 128) {
        #pragma unroll
        for (int c = 0; c < 3; ++c)
            vch2[c * 128 + tid] = pack_h2(vsm[(2 * tid) * 3 + c], vsm[(2 * tid + 1) * 3 + c]);
    }

    const uint32_t Abase = s2u(smem + OFF_A);
    const uint32_t Bbase = s2u(smem + OFF_B);

    const int wid  = tid >> 5;
    const int lane = tid & 31;
    const int w0   = wid * 48;              // warp's cw range [w0, w0+48)

    const int a_row = lane & 15;
    const int a_kb  = (lane >> 4) << 4;
    const int b_row = (((lane >> 4) & 1) << 3) + (lane & 7);
    const int b_kb  = ((lane >> 3) & 1) << 4;

    float acc[6][4];
    #pragma unroll
    for (int nb = 0; nb < 6; ++nb)
        #pragma unroll
        for (int j = 0; j < 4; ++j) acc[nb][j] = 0.f;

    // ---- 4 stages of 64 points ----
    for (int s = 0; s < 4; ++s) {
        __syncthreads();   // tables ready (s=0) / B buffer free (s>0)

        // A sub-tile: ey[h][p], 16h x 64p (tid<128: one task each)
        if (tid < 128) {
            const int h  = tid & 15;
            const int pg = tid >> 4;                  // 0..7
            const int pb = s * 64 + pg * 8;
            const float ah = a_ * (float)(hbase + h);
            float e[8];
            #pragma unroll
            for (int i = 0; i < 8; ++i) {
                const float d = ah - by[pb + i];
                e[i] = fast_exp2(-d * d);
            }
            asm volatile("st.shared.v4.b32 [%0], {%1,%2,%3,%4};"
                         :: "r"(Abase + sw128((uint32_t)(h * 128 + pg * 16))),
                            "r"(pack_h2(e[0], e[1])), "r"(pack_h2(e[2], e[3])),
                            "r"(pack_h2(e[4], e[5])), "r"(pack_h2(e[6], e[7])));
        }

        // B sub-tile: (ex*v)[cw][p], 384 rows x 64p; exps once, 3 channels via hmul2
        #pragma unroll
        for (int k = 0; k < 4; ++k) {
            const int task = tid + k * TPB;           // 0..1023
            const int w    = task & 127;
            const int pg   = task >> 7;               // 0..7 (warp-uniform)
            const int pb   = s * 64 + pg * 8;
            const float aw = a_ * (float)w;
            float e[8];
            #pragma unroll
            for (int i = 0; i < 8; ++i) {
                const float d = aw - bx[pb + i];      // broadcast
                e[i] = fast_exp2(-d * d);
            }
            uint32_t eh[4];
            #pragma unroll
            for (int j = 0; j < 4; ++j) eh[j] = pack_h2(e[2 * j], e[2 * j + 1]);
            const int pairb = s * 32 + pg * 4;        // warp-uniform
            #pragma unroll
            for (int c = 0; c < 3; ++c) {
                const uint32_t m0 = hmul2(eh[0], vch2[c * 128 + pairb]);
                const uint32_t m1 = hmul2(eh[1], vch2[c * 128 + pairb + 1]);
                const uint32_t m2 = hmul2(eh[2], vch2[c * 128 + pairb + 2]);
                const uint32_t m3 = hmul2(eh[3], vch2[c * 128 + pairb + 3]);
                asm volatile("st.shared.v4.b32 [%0], {%1,%2,%3,%4};"
                             :: "r"(Bbase + sw128((uint32_t)((c * 128 + w) * 128 + pg * 16))),
                                "r"(m0), "r"(m1), "r"(m2), "r"(m3));
            }
        }
        __syncthreads();

        // consumer: 4 K-steps; warp tile 16h x 48cw
        #pragma unroll
        for (int ks = 0; ks < 4; ++ks) {
            const uint32_t kbyte = ks * 32;

            uint32_t a0, a1, a2, a3;
            ldsm_x4(Abase + sw128((uint32_t)(a_row * 128) + kbyte + a_kb), a0, a1, a2, a3);
            uint32_t b[3][4];
            #pragma unroll
            for (int nb16 = 0; nb16 < 3; ++nb16) {
                const uint32_t row = (uint32_t)(w0 + nb16 * 16 + b_row);
                ldsm_x4(Bbase + sw128(row * 128 + kbyte + b_kb),
                        b[nb16][0], b[nb16][1], b[nb16][2], b[nb16][3]);
            }
            #pragma unroll
            for (int nb = 0; nb < 6; ++nb)
                mma16816(acc[nb], a0, a1, a2, a3,
                         b[nb >> 1][(nb & 1) ? 2 : 0], b[nb >> 1][(nb & 1) ? 3 : 1]);
        }
    }

    // ---- epilogue: red.v2 straight into out ----
    const int r  = lane >> 2;
    const int c2 = (lane & 3) * 2;
    float* on = out + ((size_t)n * 3 << 14);
    #pragma unroll
    for (int nb = 0; nb < 6; ++nb) {
        const int cw = w0 + nb * 8 + c2;
        const int c  = cw >> 7;
        const int w  = cw & 127;
        float* p = on + ((size_t)c << 14) + (hbase + r) * 128 + w;
        red_v2(p,           acc[nb][0], acc[nb][1]);
        red_v2(p + 8 * 128, acc[nb][2], acc[nb][3]);
    }
}

extern "C" void kernel_launch(void* const* d_in, const int* in_sizes, int n_in,
                              void* d_out, int out_size) {
    const float* coords = (const float*)d_in[0];   // [N,P,2]
    const float* values = (const float*)d_in[1];   // [N,P,C]
    const float* sigma  = (const float*)d_in[2];   // [N,1]

    const int N = in_sizes[2];
    const int P = in_sizes[0] / (2 * N);           // 1024

    cudaFuncSetAttribute(splat2d_hmma_kernel,
                         cudaFuncAttributeMaxDynamicSharedMemorySize, SMEM_SZ);

    cudaMemsetAsync(d_out, 0, (size_t)out_size * sizeof(float), 0);

    dim3 grid((P / 256) * 8, N);                   // 32 x 4 = 128 CTAs = one wave
    splat2d_hmma_kernel<<<grid, TPB, SMEM_SZ>>>(coords, values, sigma, (float*)d_out, P);
}

// round 12
// speedup vs baseline: 1.0337x; 1.0337x over previous
#include <cuda_runtime.h>
#include <cuda_fp16.h>
#include <cstdint>
#include <math.h>

#define TPB 512

static __device__ __forceinline__ uint32_t s2u(const void* p) {
    uint32_t a;
    asm("{ .reg .u64 t; cvta.to.shared.u64 t, %1; cvt.u32.u64 %0, t; }" : "=r"(a) : "l"(p));
    return a;
}
static __device__ __forceinline__ float fast_exp2(float x) {
    float y; asm("ex2.approx.ftz.f32 %0, %1;" : "=f"(y) : "f"(x)); return y;
}
static __device__ __forceinline__ uint32_t pack_h2(float lo, float hi) {
    uint32_t u;
    asm("cvt.rn.f16x2.f32 %0, %1, %2;" : "=r"(u) : "f"(hi), "f"(lo));  // d.lo = %2
    return u;
}
static __device__ __forceinline__ uint32_t hmul2(uint32_t a, uint32_t b) {
    uint32_t d;
    asm("mul.rn.f16x2 %0, %1, %2;" : "=r"(d) : "r"(a), "r"(b));
    return d;
}
static __device__ __forceinline__ uint32_t sw128(uint32_t off) {
    return off ^ ((off >> 3) & 0x70);
}
static __device__ __forceinline__ void ldsm_x4(uint32_t addr, uint32_t& r0, uint32_t& r1,
                                               uint32_t& r2, uint32_t& r3) {
    asm volatile("ldmatrix.sync.aligned.m8n8.x4.shared.b16 {%0,%1,%2,%3}, [%4];"
                 : "=r"(r0), "=r"(r1), "=r"(r2), "=r"(r3) : "r"(addr));
}
static __device__ __forceinline__ void mma16816(float* c, uint32_t a0, uint32_t a1,
                                                uint32_t a2, uint32_t a3,
                                                uint32_t b0, uint32_t b1) {
    asm volatile(
        "mma.sync.aligned.m16n8k16.row.col.f32.f16.f16.f32 "
        "{%0,%1,%2,%3}, {%4,%5,%6,%7}, {%8,%9}, {%0,%1,%2,%3};"
        : "+f"(c[0]), "+f"(c[1]), "+f"(c[2]), "+f"(c[3])
        : "r"(a0), "r"(a1), "r"(a2), "r"(a3), "r"(b0), "r"(b1));
}
static __device__ __forceinline__ void red_v2(float* p, float x, float y) {
    asm volatile("red.global.add.v2.f32 [%0], {%1, %2};"
                 :: "l"(p), "f"(x), "f"(y) : "memory");
}
static __device__ __forceinline__ void wg_bar(int wg) {
    asm volatile("bar.sync %0, 256;" :: "r"(wg + 1) : "memory");
}

// dynamic smem: per-wg B[384x64p SW128] + A[16x64p], then shared tables
#define OFF_B0   0          // 49152
#define OFF_B1   49152      // 49152
#define OFF_A0   98304      // 2048
#define OFF_A1   100352     // 2048
#define OFF_BX   102400     // 1024 (256 floats)
#define OFF_BY   103424     // 1024
#define OFF_VH   104448     // 1536 (3 x 128 u32 f16x2 point-pairs)
#define OFF_VS   105984     // 3072 (raw values, init only)
#define SMEM_SZ  109056

// CTA = (kp chunk of 256 points, 16-row h-tile, batch n); 128 CTAs = one wave.
// Two independent warp-groups: wg g handles K-stages {2g, 2g+1} with private buffers.
__global__ void __launch_bounds__(TPB, 1)
splat2d_hmma_kernel(const float* __restrict__ coords,   // [N,P,2]
                    const float* __restrict__ values,   // [N,P,3]
                    const float* __restrict__ sigma,    // [N,1]
                    float* __restrict__ out,            // [N,3,128,128]
                    int P) {
    extern __shared__ __align__(1024) char smem[];
    float*    bx   = (float*)(smem + OFF_BX);
    float*    by   = (float*)(smem + OFF_BY);
    uint32_t* vch2 = (uint32_t*)(smem + OFF_VH);
    float*    vsm  = (float*)(smem + OFF_VS);

    const int tid  = threadIdx.x;
    const int wg   = tid >> 8;              // warp-group 0/1
    const int wtid = tid & 255;
    const int kp   = blockIdx.x >> 3;       // 256-point chunk
    const int hq   = blockIdx.x & 7;        // 16-row tile
    const int n    = blockIdx.y;
    const int p0   = kp * 256;
    const int hbase = hq * 16;

    const float sg = sigma[n];
    const float a_ = sqrtf(0.72134752044448169f) / sg;   // sqrt(log2(e)/2)/sigma

    const float2* cb2 = (const float2*)coords + (size_t)n * P;
    const float*  vb  = values + (size_t)n * P * 3;

    // ---- stage chunk tables (all 512 threads) ----
    if (tid < 256) {
        const float2 cd = cb2[p0 + tid];
        bx[tid] = a_ * cd.x;
        by[tid] = a_ * cd.y;
    }
    for (int i = tid; i < 768; i += TPB) vsm[i] = vb[p0 * 3 + i];
    __syncthreads();
    if (tid < 128) {
        #pragma unroll
        for (int c = 0; c < 3; ++c)
            vch2[c * 128 + tid] = pack_h2(vsm[(2 * tid) * 3 + c], vsm[(2 * tid + 1) * 3 + c]);
    }
    __syncthreads();   // last full-CTA sync; wgs independent hereafter

    const uint32_t Abase = s2u(smem) + (wg ? OFF_A1 : OFF_A0);
    const uint32_t Bbase = s2u(smem) + (wg ? OFF_B1 : OFF_B0);

    const int wwid = (tid >> 5) & 7;        // warp index within wg
    const int lane = tid & 31;
    const int w0   = wwid * 48;             // warp's cw range [w0, w0+48)

    const int a_row = lane & 15;
    const int a_kb  = (lane >> 4) << 4;
    const int b_row = (((lane >> 4) & 1) << 3) + (lane & 7);
    const int b_kb  = ((lane >> 3) & 1) << 4;

    float acc[6][4];
    #pragma unroll
    for (int nb = 0; nb < 6; ++nb)
        #pragma unroll
        for (int j = 0; j < 4; ++j) acc[nb][j] = 0.f;

    // ---- 2 stages of 64 points per wg ----
    #pragma unroll
    for (int ss = 0; ss < 2; ++ss) {
        const int s = wg * 2 + ss;

        // A sub-tile: ey[h][p], 16h x 64p
        if (wtid < 128) {
            const int h  = wtid & 15;
            const int pg = wtid >> 4;
            const int pb = s * 64 + pg * 8;
            const float ah = a_ * (float)(hbase + h);
            float e[8];
            #pragma unroll
            for (int i = 0; i < 8; ++i) {
                const float d = ah - by[pb + i];
                e[i] = fast_exp2(-d * d);
            }
            asm volatile("st.shared.v4.b32 [%0], {%1,%2,%3,%4};"
                         :: "r"(Abase + sw128((uint32_t)(h * 128 + pg * 16))),
                            "r"(pack_h2(e[0], e[1])), "r"(pack_h2(e[2], e[3])),
                            "r"(pack_h2(e[4], e[5])), "r"(pack_h2(e[6], e[7])));
        }

        // B sub-tile: (ex*v)[cw][p], 384 rows x 64p; exps once, 3 channels via hmul2
        #pragma unroll
        for (int k = 0; k < 4; ++k) {
            const int task = wtid + k * 256;          // 0..1023
            const int w    = task & 127;
            const int pg   = task >> 7;               // 0..7 (warp-uniform)
            const int pb   = s * 64 + pg * 8;
            const float aw = a_ * (float)w;
            float e[8];
            #pragma unroll
            for (int i = 0; i < 8; ++i) {
                const float d = aw - bx[pb + i];      // broadcast
                e[i] = fast_exp2(-d * d);
            }
            uint32_t eh[4];
            #pragma unroll
            for (int j = 0; j < 4; ++j) eh[j] = pack_h2(e[2 * j], e[2 * j + 1]);
            const int pairb = s * 32 + pg * 4;        // warp-uniform
            #pragma unroll
            for (int c = 0; c < 3; ++c) {
                const uint32_t m0 = hmul2(eh[0], vch2[c * 128 + pairb]);
                const uint32_t m1 = hmul2(eh[1], vch2[c * 128 + pairb + 1]);
                const uint32_t m2 = hmul2(eh[2], vch2[c * 128 + pairb + 2]);
                const uint32_t m3 = hmul2(eh[3], vch2[c * 128 + pairb + 3]);
                asm volatile("st.shared.v4.b32 [%0], {%1,%2,%3,%4};"
                             :: "r"(Bbase + sw128((uint32_t)((c * 128 + w) * 128 + pg * 16))),
                                "r"(m0), "r"(m1), "r"(m2), "r"(m3));
            }
        }
        wg_bar(wg);   // this wg's tiles ready

        // consumer: 4 K-steps; warp tile 16h x 48cw
        #pragma unroll
        for (int ks = 0; ks < 4; ++ks) {
            const uint32_t kbyte = ks * 32;

            uint32_t a0, a1, a2, a3;
            ldsm_x4(Abase + sw128((uint32_t)(a_row * 128) + kbyte + a_kb), a0, a1, a2, a3);
            uint32_t b[3][4];
            #pragma unroll
            for (int nb16 = 0; nb16 < 3; ++nb16) {
                const uint32_t row = (uint32_t)(w0 + nb16 * 16 + b_row);
                ldsm_x4(Bbase + sw128(row * 128 + kbyte + b_kb),
                        b[nb16][0], b[nb16][1], b[nb16][2], b[nb16][3]);
            }
            #pragma unroll
            for (int nb = 0; nb < 6; ++nb)
                mma16816(acc[nb], a0, a1, a2, a3,
                         b[nb >> 1][(nb & 1) ? 2 : 0], b[nb >> 1][(nb & 1) ? 3 : 1]);
        }
        wg_bar(wg);   // B buffer free for next stage
    }

    // ---- epilogue: red.v2 straight into out (both wgs, K-half partials) ----
    const int r  = lane >> 2;
    const int c2 = (lane & 3) * 2;
    float* on = out + ((size_t)n * 3 << 14);
    #pragma unroll
    for (int nb = 0; nb < 6; ++nb) {
        const int cw = w0 + nb * 8 + c2;
        const int c  = cw >> 7;
        const int w  = cw & 127;
        float* p = on + ((size_t)c << 14) + (hbase + r) * 128 + w;
        red_v2(p,           acc[nb][0], acc[nb][1]);
        red_v2(p + 8 * 128, acc[nb][2], acc[nb][3]);
    }
}

extern "C" void kernel_launch(void* const* d_in, const int* in_sizes, int n_in,
                              void* d_out, int out_size) {
    const float* coords = (const float*)d_in[0];   // [N,P,2]
    const float* values = (const float*)d_in[1];   // [N,P,C]
    const float* sigma  = (const float*)d_in[2];   // [N,1]

    const int N = in_sizes[2];
    const int P = in_sizes[0] / (2 * N);           // 1024

    cudaFuncSetAttribute(splat2d_hmma_kernel,
                         cudaFuncAttributeMaxDynamicSharedMemorySize, SMEM_SZ);

    cudaMemsetAsync(d_out, 0, (size_t)out_size * sizeof(float), 0);

    dim3 grid((P / 256) * 8, N);                   // 32 x 4 = 128 CTAs = one wave
    splat2d_hmma_kernel<<<grid, TPB, SMEM_SZ>>>(coords, values, sigma, (float*)d_out, P);
}